// round 3
// baseline (speedup 1.0000x reference)
#include <cuda_runtime.h>
#include <cuda_bf16.h>
#include <math.h>

#define BSZ 2
#define DM 96
#define DI 192
#define NST 16
#define DR 6
#define KD 4
#define LL 4096
#define LOG2E 1.4426950408889634f

// ---- scratch (device globals; no runtime alloc) ----
__device__ float g_x1pre[BSZ*DI*LL];
__device__ float g_x1  [BSZ*DI*LL];
__device__ float g_x1T [BSZ*DI*LL];
__device__ float g_dt  [BSZ*KD*DI*LL];
__device__ float g_Bs  [BSZ*KD*NST*LL];
__device__ float g_Cs  [BSZ*KD*NST*LL];
__device__ float g_ys  [BSZ*KD*DI*LL];
__device__ float g_ym  [BSZ*DI*LL];
__device__ float g_yln [BSZ*LL*DI];     // [b][sp][d]
__device__ float g_A2  [KD*DI*NST];

__device__ __forceinline__ float ex2f(float x){
    float y; asm("ex2.approx.f32 %0, %1;" : "=f"(y) : "f"(x)); return y;
}

// ---- K0: A2 = -exp(A_logs)*log2e ----
__global__ void k_prep(const float* __restrict__ A_logs){
    int i = blockIdx.x*256 + threadIdx.x;
    if(i < KD*DI*NST) g_A2[i] = -__expf(A_logs[i]) * LOG2E;
}

// ---- K1: in_proj 1x1 + BN ----
__global__ void __launch_bounds__(512) k_inproj(const float* __restrict__ x,
        const float* __restrict__ w, const float* __restrict__ bg,
        const float* __restrict__ bb){
    __shared__ float xs[64*100];           // [sp][c], pad 100
    int b = blockIdx.y, sp0 = blockIdx.x*64, t = threadIdx.x;
    for(int i=t;i<DM*64;i+=512){
        int c=i>>6, sp=i&63;
        xs[sp*100+c] = x[(b*DM+c)*LL + sp0+sp];
    }
    __syncthreads();
    int sp = t&63, og = t>>6;              // 8 groups x 24 outputs
    float acc[24];
    #pragma unroll
    for(int j=0;j<24;j++) acc[j]=0.f;
    const float4* x4 = (const float4*)(xs + sp*100);
    const float* wb = w + og*24*DM;
    for(int c4=0;c4<DM/4;c4++){
        float4 xv = x4[c4];
        #pragma unroll
        for(int j=0;j<24;j++){
            float4 wv = __ldg((const float4*)(wb + j*DM + c4*4));
            acc[j] = fmaf(wv.x,xv.x,fmaf(wv.y,xv.y,fmaf(wv.z,xv.z,fmaf(wv.w,xv.w,acc[j]))));
        }
    }
    float inv = rsqrtf(1.f + 1e-5f);
    #pragma unroll
    for(int j=0;j<24;j++){
        int o = og*24+j;
        g_x1pre[(b*DI+o)*LL + sp0+sp] = acc[j]*(__ldg(bg+o)*inv) + __ldg(bb+o);
    }
}

// ---- K2: depthwise 3x3 SAME + bias + SiLU -> g_x1 and transpose g_x1T ----
__global__ void __launch_bounds__(256) k_dwconv(const float* __restrict__ dww,
        const float* __restrict__ dwb){
    __shared__ float halo[66*68];
    __shared__ float outs[64*65];
    int d = blockIdx.x, b = blockIdx.y, t = threadIdx.x;
    const float* src = g_x1pre + (b*DI+d)*LL;
    for(int i=t;i<66*66;i+=256){
        int r=i/66, c=i%66, rr=r-1, cc=c-1;
        float v=0.f;
        if((unsigned)rr<64u && (unsigned)cc<64u) v = src[rr*64+cc];
        halo[r*68+c]=v;
    }
    __syncthreads();
    float w0=__ldg(dww+d*9+0),w1=__ldg(dww+d*9+1),w2=__ldg(dww+d*9+2);
    float w3=__ldg(dww+d*9+3),w4=__ldg(dww+d*9+4),w5=__ldg(dww+d*9+5);
    float w6=__ldg(dww+d*9+6),w7=__ldg(dww+d*9+7),w8=__ldg(dww+d*9+8);
    float bias=__ldg(dwb+d);
    float* dst = g_x1 + (b*DI+d)*LL;
    for(int i=t;i<4096;i+=256){
        int h=i>>6, w=i&63;
        const float* hp = halo + h*68 + w;
        float s = hp[0]*w0+hp[1]*w1+hp[2]*w2 + hp[68]*w3+hp[69]*w4+hp[70]*w5
                + hp[136]*w6+hp[137]*w7+hp[138]*w8 + bias;
        float v = s * __fdividef(1.f, 1.f + __expf(-s));
        dst[i]=v;
        outs[h*65+w]=v;
    }
    __syncthreads();
    float* dstT = g_x1T + (b*DI+d)*LL;
    for(int i=t;i<4096;i+=256){
        int wv=i>>6, h=i&63;
        dstT[i] = outs[h*65+wv];
    }
}

// ---- K3: x_dbl projection + dt projection + softplus (scan order) ----
__global__ void __launch_bounds__(128) k_xproj(const float* __restrict__ xpw,
        const float* __restrict__ dtw, const float* __restrict__ dtb){
    __shared__ float us[32*196];   // [l][d]
    __shared__ float vs[40*33];    // [c][l]
    int l0 = blockIdx.x*32, k = blockIdx.y, b = blockIdx.z, t = threadIdx.x;
    const float* ub = ((k&1)? g_x1T : g_x1) + b*DI*LL;
    int rev = (k>=2);
    for(int i=t;i<DI*32;i+=128){
        int d=i>>5, l=i&31;
        int idx = rev ? (LL-1-(l0+l)) : (l0+l);
        us[l*196+d] = ub[d*LL + idx];
    }
    __syncthreads();
    {
        int l=t&31, ch=t>>5;       // 4 groups x 10 rows (>=38 skipped)
        float acc[10];
        #pragma unroll
        for(int j=0;j<10;j++) acc[j]=0.f;
        const float4* u4 = (const float4*)(us + l*196);
        const float* wb = xpw + (k*38 + ch*10)*DI;
        for(int d4=0; d4<DI/4; d4++){
            float4 uv = u4[d4];
            #pragma unroll
            for(int j=0;j<10;j++){
                if(ch*10+j < 38){
                    float4 wv = __ldg((const float4*)(wb + j*DI + d4*4));
                    acc[j] = fmaf(wv.x,uv.x,fmaf(wv.y,uv.y,fmaf(wv.z,uv.z,fmaf(wv.w,uv.w,acc[j]))));
                }
            }
        }
        #pragma unroll
        for(int j=0;j<10;j++){
            int c = ch*10+j;
            if(c<38) vs[c*33+l] = acc[j];
        }
    }
    __syncthreads();
    int base = ((b*KD+k)*NST)*LL;
    for(int i=t;i<2*NST*32;i+=128){
        int row=i>>5, l=i&31;
        float v = vs[(DR+row)*33+l];
        if(row<NST) g_Bs[base + row*LL + l0+l] = v;
        else        g_Cs[base + (row-NST)*LL + l0+l] = v;
    }
    {
        int l=t&31, dh=t>>5;       // 4 groups x 48 d
        float v0=vs[l],v1=vs[33+l],v2=vs[66+l],v3=vs[99+l],v4=vs[132+l],v5=vs[165+l];
        int dbase = ((b*KD+k)*DI)*LL;
        for(int dd=0;dd<48;dd++){
            int d = dh*48+dd;
            const float* wr = dtw + (k*DI+d)*DR;
            float s = __ldg(dtb + k*DI + d)
                    + __ldg(wr+0)*v0 + __ldg(wr+1)*v1 + __ldg(wr+2)*v2
                    + __ldg(wr+3)*v3 + __ldg(wr+4)*v4 + __ldg(wr+5)*v5;
            float e = __expf(-fabsf(s));
            g_dt[dbase + d*LL + l0+l] = fmaxf(s,0.f) + __logf(1.f+e);
        }
    }
}

// ---- K4: selective scan; warp = 2 channels, lane = state ----
__global__ void __launch_bounds__(32) k_scan(const float* __restrict__ Ds){
    int warp = blockIdx.x;                 // 0..767
    int lane = threadIdx.x;
    int pair = warp % (DI/2);
    int k = (warp/(DI/2)) % KD;
    int b = warp/((DI/2)*KD);
    int n = lane & 15;
    int d = pair*2 + (lane>>4);
    const float* dtp = g_dt + ((b*KD+k)*DI + d)*LL;
    const float* up  = ((k&1)? g_x1T : g_x1) + (b*DI + d)*LL;
    const float* bp  = g_Bs + ((b*KD+k)*NST + n)*LL;
    const float* cp  = g_Cs + ((b*KD+k)*NST + n)*LL;
    float* yp = g_ys + ((b*KD+k)*DI + d)*LL;
    float A2 = g_A2[(k*DI+d)*NST + n];
    float Dv = __ldg(Ds + k*DI + d);
    int rev = (k>=2);
    float h = 0.f;
    for(int s=0;s<LL;s+=4){
        float4 dt4 = *(const float4*)(dtp+s);
        float4 B4  = *(const float4*)(bp+s);
        float4 C4  = *(const float4*)(cp+s);
        float4 u4;
        if(!rev) u4 = *(const float4*)(up+s);
        else { float4 r4 = *(const float4*)(up + (LL-4-s));
               u4 = make_float4(r4.w, r4.z, r4.y, r4.x); }
        float dta[4]={dt4.x,dt4.y,dt4.z,dt4.w};
        float ua [4]={u4.x, u4.y, u4.z, u4.w};
        float Ba [4]={B4.x, B4.y, B4.z, B4.w};
        float Ca [4]={C4.x, C4.y, C4.z, C4.w};
        float ya [4];
        #pragma unroll
        for(int j=0;j<4;j++){
            float e = ex2f(dta[j]*A2);
            h = fmaf(e, h, dta[j]*ua[j]*Ba[j]);
            float p = h * Ca[j];
            p += __shfl_xor_sync(0xffffffffu, p, 1);
            p += __shfl_xor_sync(0xffffffffu, p, 2);
            p += __shfl_xor_sync(0xffffffffu, p, 4);
            p += __shfl_xor_sync(0xffffffffu, p, 8);
            ya[j] = fmaf(Dv, ua[j], p);
        }
        if(n==0) *(float4*)(yp+s) = make_float4(ya[0],ya[1],ya[2],ya[3]);
    }
}

// ---- K5: cross-merge -> g_ym [b][d][sp] ----
__global__ void __launch_bounds__(256) k_merge(){
    __shared__ float t13[32*33];
    int tile = blockIdx.x;                 // 2x2 tiles of 32x32
    int d = blockIdx.y, b = blockIdx.z, t = threadIdx.x;
    int h0=(tile>>1)*32, w0=(tile&1)*32;
    const float* y0 = g_ys + ((b*KD+0)*DI+d)*LL;
    const float* y1 = g_ys + ((b*KD+1)*DI+d)*LL;
    const float* y2 = g_ys + ((b*KD+2)*DI+d)*LL;
    const float* y3 = g_ys + ((b*KD+3)*DI+d)*LL;
    for(int i=t;i<32*32;i+=256){
        int wi=i>>5, hi=i&31;
        int spT = (w0+wi)*64 + h0+hi;
        t13[wi*33+hi] = y1[spT] + y3[LL-1-spT];
    }
    __syncthreads();
    for(int i=t;i<32*32;i+=256){
        int hi=i>>5, wi=i&31;
        int sp = (h0+hi)*64 + w0+wi;
        g_ym[(b*DI+d)*LL + sp] = y0[sp] + y2[LL-1-sp] + t13[wi*33+hi];
    }
}

// ---- K6: LayerNorm over DI; write [b][sp][d] ----
__global__ void __launch_bounds__(256) k_ln(const float* __restrict__ lng,
        const float* __restrict__ lnb){
    __shared__ float ts[DI*33];
    __shared__ float mu[32], rsd[32];
    int b = blockIdx.y, sp0 = blockIdx.x*32, t = threadIdx.x;
    for(int i=t;i<DI*32;i+=256){
        int d=i>>5, c=i&31;
        ts[d*33+c] = g_ym[(b*DI+d)*LL + sp0+c];
    }
    __syncthreads();
    if(t<32){
        float s=0.f, s2=0.f;
        for(int d=0;d<DI;d++){ float v=ts[d*33+t]; s+=v; s2=fmaf(v,v,s2); }
        float m = s*(1.f/DI);
        mu[t]=m;
        rsd[t]=rsqrtf(s2*(1.f/DI) - m*m + 1e-5f);
    }
    __syncthreads();
    for(int i=t;i<32*DI;i+=256){
        int c=i/DI, d=i%DI;
        float v=(ts[d*33+c]-mu[c])*rsd[c]*__ldg(lng+d)+__ldg(lnb+d);
        g_yln[(b*LL+sp0+c)*DI + d] = v;
    }
}

// ---- K7: out_proj 1x1 + BN -> d_out ----
__global__ void __launch_bounds__(256) k_outproj(const float* __restrict__ ow,
        const float* __restrict__ bg, const float* __restrict__ bb,
        float* __restrict__ out){
    __shared__ float ys2[32*196];          // [sp][d]
    int b = blockIdx.y, sp0 = blockIdx.x*32, t = threadIdx.x;
    for(int i=t;i<32*DI;i+=256){
        int sp=i/DI, d=i%DI;
        ys2[sp*196+d] = g_yln[(b*LL+sp0+sp)*DI + d];
    }
    __syncthreads();
    int sp = t&31, og = t>>5;              // 8 groups x 12 outputs
    float acc[12];
    #pragma unroll
    for(int j=0;j<12;j++) acc[j]=0.f;
    const float4* y4 = (const float4*)(ys2 + sp*196);
    const float* wb = ow + og*12*DI;
    for(int d4=0; d4<DI/4; d4++){
        float4 yv = y4[d4];
        #pragma unroll
        for(int j=0;j<12;j++){
            float4 wv = __ldg((const float4*)(wb + j*DI + d4*4));
            acc[j] = fmaf(wv.x,yv.x,fmaf(wv.y,yv.y,fmaf(wv.z,yv.z,fmaf(wv.w,yv.w,acc[j]))));
        }
    }
    float inv = rsqrtf(1.f + 1e-5f);
    #pragma unroll
    for(int j=0;j<12;j++){
        int o = og*12+j;
        out[(b*DM+o)*LL + sp0+sp] = acc[j]*(__ldg(bg+o)*inv) + __ldg(bb+o);
    }
}

extern "C" void kernel_launch(void* const* d_in, const int* in_sizes, int n_in,
                              void* d_out, int out_size){
    const float* x    = (const float*)d_in[0];
    const float* inw  = (const float*)d_in[1];
    const float* ibg  = (const float*)d_in[2];
    const float* ibb  = (const float*)d_in[3];
    const float* dww  = (const float*)d_in[4];
    const float* dwb  = (const float*)d_in[5];
    const float* xpw  = (const float*)d_in[6];
    const float* dtw  = (const float*)d_in[7];
    const float* dtb  = (const float*)d_in[8];
    const float* alog = (const float*)d_in[9];
    const float* Ds   = (const float*)d_in[10];
    const float* lng  = (const float*)d_in[11];
    const float* lnb  = (const float*)d_in[12];
    const float* ow   = (const float*)d_in[13];
    const float* obg  = (const float*)d_in[14];
    const float* obb  = (const float*)d_in[15];
    float* out = (float*)d_out;

    k_prep<<<(KD*DI*NST+255)/256, 256>>>(alog);
    k_inproj<<<dim3(64,BSZ), 512>>>(x, inw, ibg, ibb);
    k_dwconv<<<dim3(DI,BSZ), 256>>>(dww, dwb);
    k_xproj<<<dim3(LL/32, KD, BSZ), 128>>>(xpw, dtw, dtb);
    k_scan<<<BSZ*KD*(DI/2), 32>>>(Ds);
    k_merge<<<dim3(4, DI, BSZ), 256>>>();
    k_ln<<<dim3(LL/32, BSZ), 256>>>(lng, lnb);
    k_outproj<<<dim3(LL/32, BSZ), 256>>>(ow, obg, obb, out);
}

// round 6
// speedup vs baseline: 1.0359x; 1.0359x over previous
#include <cuda_runtime.h>
#include <cuda_bf16.h>
#include <math.h>

#define BSZ 2
#define DM 96
#define DI 192
#define NST 16
#define DR 6
#define KD 4
#define LL 4096
#define LOG2E 1.4426950408889634f

// ---- scratch (device globals; no runtime alloc) ----
__device__ float g_x1pre[BSZ*DI*LL];
__device__ float g_x1  [BSZ*DI*LL];
__device__ float g_x1T [BSZ*DI*LL];
__device__ float g_dt  [BSZ*KD*DI*LL];
__device__ float g_Bs  [BSZ*KD*NST*LL];
__device__ float g_Cs  [BSZ*KD*NST*LL];
__device__ float g_ys  [BSZ*KD*DI*LL];
__device__ float g_ym  [BSZ*DI*LL];
__device__ float g_yln [BSZ*LL*DI];     // [b][sp][d]

__device__ __forceinline__ float ex2f(float x){
    float y; asm("ex2.approx.f32 %0, %1;" : "=f"(y) : "f"(x)); return y;
}

// ---- K1: in_proj 1x1 + BN ----
__global__ void __launch_bounds__(512) k_inproj(const float* __restrict__ x,
        const float* __restrict__ w, const float* __restrict__ bg,
        const float* __restrict__ bb){
    __shared__ float xs[64*100];           // [sp][c], pad 100
    int b = blockIdx.y, sp0 = blockIdx.x*64, t = threadIdx.x;
    for(int i=t;i<DM*64;i+=512){
        int c=i>>6, sp=i&63;
        xs[sp*100+c] = x[(b*DM+c)*LL + sp0+sp];
    }
    __syncthreads();
    int sp = t&63, og = t>>6;              // 8 groups x 24 outputs
    float acc[24];
    #pragma unroll
    for(int j=0;j<24;j++) acc[j]=0.f;
    const float4* x4 = (const float4*)(xs + sp*100);
    const float* wb = w + og*24*DM;
    for(int c4=0;c4<DM/4;c4++){
        float4 xv = x4[c4];
        #pragma unroll
        for(int j=0;j<24;j++){
            float4 wv = __ldg((const float4*)(wb + j*DM + c4*4));
            acc[j] = fmaf(wv.x,xv.x,fmaf(wv.y,xv.y,fmaf(wv.z,xv.z,fmaf(wv.w,xv.w,acc[j]))));
        }
    }
    float inv = rsqrtf(1.f + 1e-5f);
    #pragma unroll
    for(int j=0;j<24;j++){
        int o = og*24+j;
        g_x1pre[(b*DI+o)*LL + sp0+sp] = acc[j]*(__ldg(bg+o)*inv) + __ldg(bb+o);
    }
}

// ---- K2: depthwise 3x3 SAME + bias + SiLU -> g_x1 and transpose g_x1T ----
__global__ void __launch_bounds__(256) k_dwconv(const float* __restrict__ dww,
        const float* __restrict__ dwb){
    __shared__ float halo[66*68];
    __shared__ float outs[64*65];
    int d = blockIdx.x, b = blockIdx.y, t = threadIdx.x;
    const float* src = g_x1pre + (b*DI+d)*LL;
    for(int i=t;i<66*66;i+=256){
        int r=i/66, c=i%66, rr=r-1, cc=c-1;
        float v=0.f;
        if((unsigned)rr<64u && (unsigned)cc<64u) v = src[rr*64+cc];
        halo[r*68+c]=v;
    }
    __syncthreads();
    float w0=__ldg(dww+d*9+0),w1=__ldg(dww+d*9+1),w2=__ldg(dww+d*9+2);
    float w3=__ldg(dww+d*9+3),w4=__ldg(dww+d*9+4),w5=__ldg(dww+d*9+5);
    float w6=__ldg(dww+d*9+6),w7=__ldg(dww+d*9+7),w8=__ldg(dww+d*9+8);
    float bias=__ldg(dwb+d);
    float* dst = g_x1 + (b*DI+d)*LL;
    for(int i=t;i<4096;i+=256){
        int h=i>>6, w=i&63;
        const float* hp = halo + h*68 + w;
        float s = hp[0]*w0+hp[1]*w1+hp[2]*w2 + hp[68]*w3+hp[69]*w4+hp[70]*w5
                + hp[136]*w6+hp[137]*w7+hp[138]*w8 + bias;
        float v = s * __fdividef(1.f, 1.f + __expf(-s));
        dst[i]=v;
        outs[h*65+w]=v;
    }
    __syncthreads();
    float* dstT = g_x1T + (b*DI+d)*LL;
    for(int i=t;i<4096;i+=256){
        int wv=i>>6, h=i&63;
        dstT[i] = outs[h*65+wv];
    }
}

// ---- K3: x_dbl projection + dt projection + softplus (scan order) ----
__global__ void __launch_bounds__(256) k_xproj(const float* __restrict__ xpw,
        const float* __restrict__ dtw, const float* __restrict__ dtb){
    __shared__ float us[32*196];   // [l][d]
    __shared__ float vs[40*33];    // [c][l]
    __shared__ float dtws[DI*DR];  // dt proj weights for this k
    __shared__ float dtbs[DI];
    int l0 = blockIdx.x*32, k = blockIdx.y, b = blockIdx.z, t = threadIdx.x;
    const float* ub = ((k&1)? g_x1T : g_x1) + b*DI*LL;
    int rev = (k>=2);
    for(int i=t;i<DI*32;i+=256){
        int d=i>>5, l=i&31;
        int idx = rev ? (LL-1-(l0+l)) : (l0+l);
        us[l*196+d] = ub[d*LL + idx];
    }
    for(int i=t;i<DI*DR;i+=256) dtws[i] = dtw[k*DI*DR + i];
    for(int i=t;i<DI;i+=256)    dtbs[i] = dtb[k*DI + i];
    __syncthreads();
    {
        int l=t&31, g=t>>5;        // 8 groups x 5 rows (>=38 skipped)
        float acc[5];
        #pragma unroll
        for(int j=0;j<5;j++) acc[j]=0.f;
        const float4* u4 = (const float4*)(us + l*196);
        const float* wb = xpw + (k*38 + g*5)*DI;
        for(int d4=0; d4<DI/4; d4++){
            float4 uv = u4[d4];
            #pragma unroll
            for(int j=0;j<5;j++){
                if(g*5+j < 38){
                    float4 wv = __ldg((const float4*)(wb + j*DI + d4*4));
                    acc[j] = fmaf(wv.x,uv.x,fmaf(wv.y,uv.y,fmaf(wv.z,uv.z,fmaf(wv.w,uv.w,acc[j]))));
                }
            }
        }
        #pragma unroll
        for(int j=0;j<5;j++){
            int c = g*5+j;
            if(c<38) vs[c*33+l] = acc[j];
        }
    }
    __syncthreads();
    int base = ((b*KD+k)*NST)*LL;
    for(int i=t;i<2*NST*32;i+=256){
        int row=i>>5, l=i&31;
        float v = vs[(DR+row)*33+l];
        if(row<NST) g_Bs[base + row*LL + l0+l] = v;
        else        g_Cs[base + (row-NST)*LL + l0+l] = v;
    }
    {
        int l=t&31, g=t>>5;        // 8 groups x 24 d
        float v0=vs[l],v1=vs[33+l],v2=vs[66+l],v3=vs[99+l],v4=vs[132+l],v5=vs[165+l];
        int dbase = ((b*KD+k)*DI)*LL;
        #pragma unroll 4
        for(int dd=0;dd<24;dd++){
            int d = g*24+dd;
            const float* wr = dtws + d*DR;
            float s = dtbs[d]
                    + wr[0]*v0 + wr[1]*v1 + wr[2]*v2
                    + wr[3]*v3 + wr[4]*v4 + wr[5]*v5;
            float e = __expf(-fabsf(s));
            g_dt[dbase + d*LL + l0+l] = fmaxf(s,0.f) + __logf(1.f+e);
        }
    }
}

// ---- K4: selective scan; warp = 2 channels, lane = state; prefetch pipeline ----
__device__ __forceinline__ void ld8(const float* p, int s, float v[8]){
    float4 a = *(const float4*)(p+s), b = *(const float4*)(p+s+4);
    v[0]=a.x; v[1]=a.y; v[2]=a.z; v[3]=a.w;
    v[4]=b.x; v[5]=b.y; v[6]=b.z; v[7]=b.w;
}
__device__ __forceinline__ void ld8r(const float* p, int s, int rev, float v[8]){
    if(!rev){ ld8(p,s,v); }
    else {
        float4 a = *(const float4*)(p+LL-8-s), b = *(const float4*)(p+LL-4-s);
        v[0]=b.w; v[1]=b.z; v[2]=b.y; v[3]=b.x;
        v[4]=a.w; v[5]=a.z; v[6]=a.y; v[7]=a.x;
    }
}
__global__ void __launch_bounds__(32) k_scan(const float* __restrict__ Ds,
                                             const float* __restrict__ A_logs){
    int warp = blockIdx.x;                 // 0..767
    int lane = threadIdx.x;
    int pair = warp % (DI/2);
    int k = (warp/(DI/2)) % KD;
    int b = warp/((DI/2)*KD);
    int n = lane & 15;
    int d = pair*2 + (lane>>4);
    const float* dtp = g_dt + ((b*KD+k)*DI + d)*LL;
    const float* up  = ((k&1)? g_x1T : g_x1) + (b*DI + d)*LL;
    const float* bp  = g_Bs + ((b*KD+k)*NST + n)*LL;
    const float* cp  = g_Cs + ((b*KD+k)*NST + n)*LL;
    float* yp = g_ys + ((b*KD+k)*DI + d)*LL;
    float A2 = -__expf(__ldg(A_logs + (k*DI+d)*NST + n)) * LOG2E;
    float Dv = __ldg(Ds + k*DI + d);
    int rev = (k>=2);
    float h = 0.f;
    float dtn[8], un[8], Bn[8], Cn[8];
    ld8(dtp,0,dtn); ld8(bp,0,Bn); ld8(cp,0,Cn); ld8r(up,0,rev,un);
    for(int s=0;s<LL;s+=8){
        float dtc[8], uc[8], Bc[8], Cc[8];
        #pragma unroll
        for(int j=0;j<8;j++){ dtc[j]=dtn[j]; uc[j]=un[j]; Bc[j]=Bn[j]; Cc[j]=Cn[j]; }
        int sn = s+8;
        if(sn < LL){ ld8(dtp,sn,dtn); ld8(bp,sn,Bn); ld8(cp,sn,Cn); ld8r(up,sn,rev,un); }
        float ya[8];
        #pragma unroll
        for(int j=0;j<8;j++){
            float e = ex2f(dtc[j]*A2);
            h = fmaf(e, h, dtc[j]*uc[j]*Bc[j]);
            float p = h * Cc[j];
            p += __shfl_xor_sync(0xffffffffu, p, 1);
            p += __shfl_xor_sync(0xffffffffu, p, 2);
            p += __shfl_xor_sync(0xffffffffu, p, 4);
            p += __shfl_xor_sync(0xffffffffu, p, 8);
            ya[j] = fmaf(Dv, uc[j], p);
        }
        if(n==0){
            *(float4*)(yp+s)   = make_float4(ya[0],ya[1],ya[2],ya[3]);
            *(float4*)(yp+s+4) = make_float4(ya[4],ya[5],ya[6],ya[7]);
        }
    }
}

// ---- K5: cross-merge -> g_ym [b][d][sp] ----
__global__ void __launch_bounds__(256) k_merge(){
    __shared__ float t13[32*33];
    int tile = blockIdx.x;                 // 2x2 tiles of 32x32
    int d = blockIdx.y, b = blockIdx.z, t = threadIdx.x;
    int h0=(tile>>1)*32, w0=(tile&1)*32;
    const float* y0 = g_ys + ((b*KD+0)*DI+d)*LL;
    const float* y1 = g_ys + ((b*KD+1)*DI+d)*LL;
    const float* y2 = g_ys + ((b*KD+2)*DI+d)*LL;
    const float* y3 = g_ys + ((b*KD+3)*DI+d)*LL;
    for(int i=t;i<32*32;i+=256){
        int wi=i>>5, hi=i&31;
        int spT = (w0+wi)*64 + h0+hi;
        t13[wi*33+hi] = y1[spT] + y3[LL-1-spT];
    }
    __syncthreads();
    for(int i=t;i<32*32;i+=256){
        int hi=i>>5, wi=i&31;
        int sp = (h0+hi)*64 + w0+wi;
        g_ym[(b*DI+d)*LL + sp] = y0[sp] + y2[LL-1-sp] + t13[wi*33+hi];
    }
}

// ---- K6: LayerNorm over DI; write [b][sp][d] ----
__global__ void __launch_bounds__(256) k_ln(const float* __restrict__ lng,
        const float* __restrict__ lnb){
    __shared__ float ts[DI*33];
    __shared__ float mu[32], rsd[32];
    int b = blockIdx.y, sp0 = blockIdx.x*32, t = threadIdx.x;
    for(int i=t;i<DI*32;i+=256){
        int d=i>>5, c=i&31;
        ts[d*33+c] = g_ym[(b*DI+d)*LL + sp0+c];
    }
    __syncthreads();
    if(t<32){
        float s=0.f, s2=0.f;
        for(int d=0;d<DI;d++){ float v=ts[d*33+t]; s+=v; s2=fmaf(v,v,s2); }
        float m = s*(1.f/DI);
        mu[t]=m;
        rsd[t]=rsqrtf(s2*(1.f/DI) - m*m + 1e-5f);
    }
    __syncthreads();
    for(int i=t;i<32*DI;i+=256){
        int c=i/DI, d=i%DI;
        float v=(ts[d*33+c]-mu[c])*rsd[c]*__ldg(lng+d)+__ldg(lnb+d);
        g_yln[(b*LL+sp0+c)*DI + d] = v;
    }
}

// ---- K7: out_proj 1x1 + BN -> d_out ----
__global__ void __launch_bounds__(256) k_outproj(const float* __restrict__ ow,
        const float* __restrict__ bg, const float* __restrict__ bb,
        float* __restrict__ out){
    __shared__ float ys2[32*196];          // [sp][d]
    int b = blockIdx.y, sp0 = blockIdx.x*32, t = threadIdx.x;
    for(int i=t;i<32*DI;i+=256){
        int sp=i/DI, d=i%DI;
        ys2[sp*196+d] = g_yln[(b*LL+sp0+sp)*DI + d];
    }
    __syncthreads();
    int sp = t&31, og = t>>5;              // 8 groups x 12 outputs
    float acc[12];
    #pragma unroll
    for(int j=0;j<12;j++) acc[j]=0.f;
    const float4* y4 = (const float4*)(ys2 + sp*196);
    const float* wb = ow + og*12*DI;
    for(int d4=0; d4<DI/4; d4++){
        float4 yv = y4[d4];
        #pragma unroll
        for(int j=0;j<12;j++){
            float4 wv = __ldg((const float4*)(wb + j*DI + d4*4));
            acc[j] = fmaf(wv.x,yv.x,fmaf(wv.y,yv.y,fmaf(wv.z,yv.z,fmaf(wv.w,yv.w,acc[j]))));
        }
    }
    float inv = rsqrtf(1.f + 1e-5f);
    #pragma unroll
    for(int j=0;j<12;j++){
        int o = og*12+j;
        out[(b*DM+o)*LL + sp0+sp] = acc[j]*(__ldg(bg+o)*inv) + __ldg(bb+o);
    }
}

extern "C" void kernel_launch(void* const* d_in, const int* in_sizes, int n_in,
                              void* d_out, int out_size){
    const float* x    = (const float*)d_in[0];
    const float* inw  = (const float*)d_in[1];
    const float* ibg  = (const float*)d_in[2];
    const float* ibb  = (const float*)d_in[3];
    const float* dww  = (const float*)d_in[4];
    const float* dwb  = (const float*)d_in[5];
    const float* xpw  = (const float*)d_in[6];
    const float* dtw  = (const float*)d_in[7];
    const float* dtb  = (const float*)d_in[8];
    const float* alog = (const float*)d_in[9];
    const float* Ds   = (const float*)d_in[10];
    const float* lng  = (const float*)d_in[11];
    const float* lnb  = (const float*)d_in[12];
    const float* ow   = (const float*)d_in[13];
    const float* obg  = (const float*)d_in[14];
    const float* obb  = (const float*)d_in[15];
    float* out = (float*)d_out;

    k_inproj<<<dim3(64,BSZ), 512>>>(x, inw, ibg, ibb);
    k_dwconv<<<dim3(DI,BSZ), 256>>>(dww, dwb);
    k_xproj<<<dim3(LL/32, KD, BSZ), 256>>>(xpw, dtw, dtb);
    k_scan<<<BSZ*KD*(DI/2), 32>>>(Ds, alog);
    k_merge<<<dim3(4, DI, BSZ), 256>>>();
    k_ln<<<dim3(LL/32, BSZ), 256>>>(lng, lnb);
    k_outproj<<<dim3(LL/32, BSZ), 256>>>(ow, obg, obb, out);
}